// round 1
// baseline (speedup 1.0000x reference)
#include <cuda_runtime.h>

#define NN 100000
#define NE 1600000
#define F_IN 64
#define F_HID 64
#define F_OUT 32

// ---- scratch (device globals; no allocation allowed) ----
__device__ float g_h1  [NN * F_HID];   // (x*outnorm)@W1, gathered by SpMM1
__device__ float g_agg1[NN * F_HID];   // scatter target layer 1
__device__ float g_h2  [NN * F_OUT];   // (relu(...)*outnorm)@W2
__device__ float g_agg2[NN * F_OUT];   // scatter target layer 2
__device__ float g_outnorm[NN];
__device__ float g_innorm [NN];
__device__ int   g_degs[NN];
__device__ int   g_degd[NN];

// ---- zero scratch each call (agg buffers + degree counters) ----
__global__ void k_zero() {
    int i = blockIdx.x * blockDim.x + threadIdx.x;
    float4 z = make_float4(0.f, 0.f, 0.f, 0.f);
    if (i < NN * F_HID / 4) {                       // 1,600,000 float4
        reinterpret_cast<float4*>(g_agg1)[i] = z;
    } else if (i < NN * F_HID / 4 + NN * F_OUT / 4) {
        reinterpret_cast<float4*>(g_agg2)[i - NN * F_HID / 4] = z;
    }
    if (i < NN) { g_degs[i] = 0; g_degd[i] = 0; }
}

// ---- degrees ----
__global__ void k_deg(const int* __restrict__ src, const int* __restrict__ dst) {
    int e = blockIdx.x * blockDim.x + threadIdx.x;
    if (e < NE) {
        atomicAdd(&g_degs[src[e]], 1);
        atomicAdd(&g_degd[dst[e]], 1);
    }
}

// ---- norms: deg^-1/2 with clamp(>=1) ----
__global__ void k_norm() {
    int i = blockIdx.x * blockDim.x + threadIdx.x;
    if (i < NN) {
        int ds = g_degs[i]; if (ds < 1) ds = 1;
        int dd = g_degd[i]; if (dd < 1) dd = 1;
        g_outnorm[i] = rsqrtf((float)ds);
        g_innorm[i]  = rsqrtf((float)dd);
    }
}

// ---- GEMM1: h1[n][j] = sum_k (x[n][k]*outnorm[n]) * W1[k][j]   (64x64) ----
// Block: 256 threads, tile 64 nodes x 64 outputs; thread tile 4x4.
__global__ __launch_bounds__(256) void k_gemm1(const float* __restrict__ x,
                                               const float* __restrict__ W1) {
    __shared__ float Ws[64 * 64];
    __shared__ float xs[64][68];   // [k][node], +4 pad keeps 16B alignment, spreads banks
    int tid = threadIdx.x;
    int nb  = blockIdx.x * 64;

    // Load W1 (4096 floats = 1024 float4)
    #pragma unroll
    for (int r = 0; r < 4; r++) {
        int idx = tid + r * 256;
        reinterpret_cast<float4*>(Ws)[idx] =
            reinterpret_cast<const float4*>(W1)[idx];
    }
    // Stage x (transposed, scaled by outnorm): 64 nodes x 16 float4
    #pragma unroll
    for (int r = 0; r < 4; r++) {
        int idx = tid + r * 256;         // 0..1023
        int n = idx >> 4, k4 = idx & 15;
        int node = nb + n;
        float4 v = make_float4(0.f, 0.f, 0.f, 0.f);
        float s = 0.f;
        if (node < NN) {
            v = reinterpret_cast<const float4*>(x)[node * 16 + k4];
            s = g_outnorm[node];
        }
        xs[k4 * 4 + 0][n] = v.x * s;
        xs[k4 * 4 + 1][n] = v.y * s;
        xs[k4 * 4 + 2][n] = v.z * s;
        xs[k4 * 4 + 3][n] = v.w * s;
    }
    __syncthreads();

    int tx = tid & 15;   // output group: j = tx*4
    int ty = tid >> 4;   // node group:   n = ty*4
    float acc[4][4] = {};
    #pragma unroll
    for (int k = 0; k < 64; k++) {
        float4 wv = *reinterpret_cast<const float4*>(&Ws[k * 64 + tx * 4]);
        float4 xv = *reinterpret_cast<const float4*>(&xs[k][ty * 4]);
        float xr[4] = {xv.x, xv.y, xv.z, xv.w};
        float wr[4] = {wv.x, wv.y, wv.z, wv.w};
        #pragma unroll
        for (int i = 0; i < 4; i++)
            #pragma unroll
            for (int j = 0; j < 4; j++)
                acc[i][j] += xr[i] * wr[j];
    }
    #pragma unroll
    for (int i = 0; i < 4; i++) {
        int node = nb + ty * 4 + i;
        if (node < NN) {
            float4 o = make_float4(acc[i][0], acc[i][1], acc[i][2], acc[i][3]);
            reinterpret_cast<float4*>(g_h1)[node * 16 + tx] = o;
        }
    }
}

// ---- SpMM1: agg1[dst] += h1[src], 64 floats/edge, thread = (edge, float4-chunk) ----
__global__ void k_spmm1(const int* __restrict__ src, const int* __restrict__ dst) {
    int t = blockIdx.x * blockDim.x + threadIdx.x;
    if (t >= NE * 16) return;
    int e = t >> 4, c = t & 15;
    int s = __ldg(&src[e]);
    int d = __ldg(&dst[e]);
    float4 v = reinterpret_cast<const float4*>(g_h1)[s * 16 + c];
    float* p = &g_agg1[d * 64 + c * 4];
    atomicAdd(p + 0, v.x);
    atomicAdd(p + 1, v.y);
    atomicAdd(p + 2, v.z);
    atomicAdd(p + 3, v.w);
}

// ---- Fused layer-1 epilogue + GEMM2:
//   t[n][k] = relu(agg1[n][k]*innorm[n] + b1[k]) * outnorm[n]
//   h2[n][j] = sum_k t[n][k] * W2[k][j]        (64 -> 32)
// Block: 256 threads, tile 64 nodes x 32 outputs; thread tile 2 nodes x 4 outs.
__global__ __launch_bounds__(256) void k_gemm2(const float* __restrict__ W2,
                                               const float* __restrict__ b1) {
    __shared__ float Ws[64 * 32];
    __shared__ float xs[64][68];
    int tid = threadIdx.x;
    int nb  = blockIdx.x * 64;

    // Load W2 (2048 floats = 512 float4)
    #pragma unroll
    for (int r = 0; r < 2; r++) {
        int idx = tid + r * 256;
        reinterpret_cast<float4*>(Ws)[idx] =
            reinterpret_cast<const float4*>(W2)[idx];
    }
    // Stage activations (transposed)
    #pragma unroll
    for (int r = 0; r < 4; r++) {
        int idx = tid + r * 256;
        int n = idx >> 4, k4 = idx & 15;
        int node = nb + n;
        float4 v = make_float4(0.f, 0.f, 0.f, 0.f);
        if (node < NN) {
            v = reinterpret_cast<const float4*>(g_agg1)[node * 16 + k4];
            float in_n = g_innorm[node];
            float on   = g_outnorm[node];
            float4 bb  = reinterpret_cast<const float4*>(b1)[k4];
            v.x = fmaxf(fmaf(v.x, in_n, bb.x), 0.f) * on;
            v.y = fmaxf(fmaf(v.y, in_n, bb.y), 0.f) * on;
            v.z = fmaxf(fmaf(v.z, in_n, bb.z), 0.f) * on;
            v.w = fmaxf(fmaf(v.w, in_n, bb.w), 0.f) * on;
        }
        xs[k4 * 4 + 0][n] = v.x;
        xs[k4 * 4 + 1][n] = v.y;
        xs[k4 * 4 + 2][n] = v.z;
        xs[k4 * 4 + 3][n] = v.w;
    }
    __syncthreads();

    int tx = tid & 7;    // output group: j = tx*4 (0..28)
    int ty = tid >> 3;   // node group:   n = ty*2 (0..62)
    float acc[2][4] = {};
    #pragma unroll
    for (int k = 0; k < 64; k++) {
        float4 wv = *reinterpret_cast<const float4*>(&Ws[k * 32 + tx * 4]);
        float x0 = xs[k][ty * 2 + 0];
        float x1 = xs[k][ty * 2 + 1];
        acc[0][0] += x0 * wv.x; acc[0][1] += x0 * wv.y;
        acc[0][2] += x0 * wv.z; acc[0][3] += x0 * wv.w;
        acc[1][0] += x1 * wv.x; acc[1][1] += x1 * wv.y;
        acc[1][2] += x1 * wv.z; acc[1][3] += x1 * wv.w;
    }
    #pragma unroll
    for (int i = 0; i < 2; i++) {
        int node = nb + ty * 2 + i;
        if (node < NN) {
            float4 o = make_float4(acc[i][0], acc[i][1], acc[i][2], acc[i][3]);
            reinterpret_cast<float4*>(g_h2)[node * 8 + tx] = o;
        }
    }
}

// ---- SpMM2: agg2[dst] += h2[src], 32 floats/edge ----
__global__ void k_spmm2(const int* __restrict__ src, const int* __restrict__ dst) {
    int t = blockIdx.x * blockDim.x + threadIdx.x;
    if (t >= NE * 8) return;
    int e = t >> 3, c = t & 7;
    int s = __ldg(&src[e]);
    int d = __ldg(&dst[e]);
    float4 v = reinterpret_cast<const float4*>(g_h2)[s * 8 + c];
    float* p = &g_agg2[d * 32 + c * 4];
    atomicAdd(p + 0, v.x);
    atomicAdd(p + 1, v.y);
    atomicAdd(p + 2, v.z);
    atomicAdd(p + 3, v.w);
}

// ---- final: out[n][j] = agg2[n][j]*innorm[n] + b2[j] ----
__global__ void k_final(const float* __restrict__ b2, float* __restrict__ out) {
    int i = blockIdx.x * blockDim.x + threadIdx.x;   // float4 index
    if (i >= NN * F_OUT / 4) return;
    int node = i >> 3;
    int j4   = i & 7;
    float4 v  = reinterpret_cast<const float4*>(g_agg2)[i];
    float4 bb = reinterpret_cast<const float4*>(b2)[j4];
    float in_n = g_innorm[node];
    float4 o;
    o.x = fmaf(v.x, in_n, bb.x);
    o.y = fmaf(v.y, in_n, bb.y);
    o.z = fmaf(v.z, in_n, bb.z);
    o.w = fmaf(v.w, in_n, bb.w);
    reinterpret_cast<float4*>(out)[i] = o;
}

extern "C" void kernel_launch(void* const* d_in, const int* in_sizes, int n_in,
                              void* d_out, int out_size) {
    const float* x   = (const float*)d_in[0];
    const int*   src = (const int*)  d_in[1];
    const int*   dst = (const int*)  d_in[2];
    const float* W1  = (const float*)d_in[3];
    const float* b1  = (const float*)d_in[4];
    const float* W2  = (const float*)d_in[5];
    const float* b2  = (const float*)d_in[6];
    float* out = (float*)d_out;

    const int T = 256;
    int zero_n = NN * F_HID / 4 + NN * F_OUT / 4;    // 2.4M threads (covers NN too)
    k_zero <<<(zero_n + T - 1) / T, T>>>();
    k_deg  <<<(NE + T - 1) / T, T>>>(src, dst);
    k_norm <<<(NN + T - 1) / T, T>>>();
    k_gemm1<<<(NN + 63) / 64, 256>>>(x, W1);
    k_spmm1<<<(NE * 16 + T - 1) / T, T>>>(src, dst);
    k_gemm2<<<(NN + 63) / 64, 256>>>(W2, b1);
    k_spmm2<<<(NE * 8 + T - 1) / T, T>>>(src, dst);
    k_final<<<(NN * F_OUT / 4 + T - 1) / T, T>>>(b2, out);
}

// round 2
// speedup vs baseline: 2.2713x; 2.2713x over previous
#include <cuda_runtime.h>

#define NN 100000
#define NE 1600000
#define F_IN 64
#define F_HID 64
#define F_OUT 32

#define SCAN_BLK 1024                      // elements per scan block (256 thr x 4)
#define SCAN_NBLK ((NN + SCAN_BLK - 1) / SCAN_BLK)   // 98

// ---- scratch (device globals; no allocation allowed) ----
__device__ float g_h1  [NN * F_HID];   // (x*outnorm)@W1, gathered by SpMM1
__device__ float g_agg1[NN * F_HID];   // gather target layer 1
__device__ float g_h2  [NN * F_OUT];   // (relu(...)*outnorm)@W2
__device__ float g_outnorm[NN];
__device__ float g_innorm [NN];
__device__ int   g_degs[NN];
__device__ int   g_degd[NN];
__device__ int   g_rowptr[NN + 1];
__device__ int   g_cursor[NN];
__device__ int   g_csr_src[NE];
__device__ int   g_blocksums[SCAN_NBLK];

// ---- zero degree counters ----
__global__ void k_zero() {
    int i = blockIdx.x * blockDim.x + threadIdx.x;
    if (i < NN) { g_degs[i] = 0; g_degd[i] = 0; }
}

// ---- degrees ----
__global__ void k_deg(const int* __restrict__ src, const int* __restrict__ dst) {
    int e = blockIdx.x * blockDim.x + threadIdx.x;
    if (e < NE) {
        atomicAdd(&g_degs[src[e]], 1);
        atomicAdd(&g_degd[dst[e]], 1);
    }
}

// ---- norms: deg^-1/2 with clamp(>=1) ----
__global__ void k_norm() {
    int i = blockIdx.x * blockDim.x + threadIdx.x;
    if (i < NN) {
        int ds = g_degs[i]; if (ds < 1) ds = 1;
        int dd = g_degd[i]; if (dd < 1) dd = 1;
        g_outnorm[i] = rsqrtf((float)ds);
        g_innorm[i]  = rsqrtf((float)dd);
    }
}

// ---- scan stage 1: per-block exclusive scan of dst-degrees (1024 elems/block) ----
__global__ __launch_bounds__(256) void k_scan1() {
    __shared__ int wsum[8];
    int t = threadIdx.x, b = blockIdx.x;
    int base = b * SCAN_BLK + t * 4;
    int v0 = 0, v1 = 0, v2 = 0, v3 = 0;
    if (base + 0 < NN) v0 = g_degd[base + 0];
    if (base + 1 < NN) v1 = g_degd[base + 1];
    if (base + 2 < NN) v2 = g_degd[base + 2];
    if (base + 3 < NN) v3 = g_degd[base + 3];
    int sum = v0 + v1 + v2 + v3;

    int lane = t & 31, wid = t >> 5;
    int x = sum;
    #pragma unroll
    for (int o = 1; o < 32; o <<= 1) {
        int y = __shfl_up_sync(0xffffffffu, x, o);
        if (lane >= o) x += y;
    }
    if (lane == 31) wsum[wid] = x;
    __syncthreads();
    if (wid == 0 && lane < 8) {
        int w = wsum[lane];
        #pragma unroll
        for (int o = 1; o < 8; o <<= 1) {
            int y = __shfl_up_sync(0x000000ffu, w, o);
            if (lane >= o) w += y;
        }
        wsum[lane] = w;
    }
    __syncthreads();
    int incl = x + (wid > 0 ? wsum[wid - 1] : 0);
    int excl = incl - sum;

    if (base + 0 < NN) g_rowptr[base + 0] = excl;
    if (base + 1 < NN) g_rowptr[base + 1] = excl + v0;
    if (base + 2 < NN) g_rowptr[base + 2] = excl + v0 + v1;
    if (base + 3 < NN) g_rowptr[base + 3] = excl + v0 + v1 + v2;
    if (t == 255) g_blocksums[b] = incl;
}

// ---- scan stage 2: exclusive scan of the 98 block sums (one block) ----
__global__ __launch_bounds__(128) void k_scan2() {
    __shared__ int wsum[4];
    int t = threadIdx.x;
    int v = (t < SCAN_NBLK) ? g_blocksums[t] : 0;
    int lane = t & 31, wid = t >> 5;
    int x = v;
    #pragma unroll
    for (int o = 1; o < 32; o <<= 1) {
        int y = __shfl_up_sync(0xffffffffu, x, o);
        if (lane >= o) x += y;
    }
    if (lane == 31) wsum[wid] = x;
    __syncthreads();
    if (wid == 0 && lane < 4) {
        int w = wsum[lane];
        #pragma unroll
        for (int o = 1; o < 4; o <<= 1) {
            int y = __shfl_up_sync(0x0000000fu, w, o);
            if (lane >= o) w += y;
        }
        wsum[lane] = w;
    }
    __syncthreads();
    int incl = x + (wid > 0 ? wsum[wid - 1] : 0);
    if (t < SCAN_NBLK) g_blocksums[t] = incl - v;
}

// ---- scan stage 3: add block offsets, init cursors ----
__global__ void k_scan3() {
    int i = blockIdx.x * blockDim.x + threadIdx.x;
    if (i < NN) {
        int r = g_rowptr[i] + g_blocksums[i >> 10];
        g_rowptr[i] = r;
        g_cursor[i] = r;
    }
    if (i == 0) g_rowptr[NN] = NE;
}

// ---- bucket: CSR adjacency (src ids grouped by dst) ----
__global__ void k_bucket(const int* __restrict__ src, const int* __restrict__ dst) {
    int e = blockIdx.x * blockDim.x + threadIdx.x;
    if (e < NE) {
        int pos = atomicAdd(&g_cursor[dst[e]], 1);
        g_csr_src[pos] = src[e];
    }
}

// ---- GEMM1: h1[n][j] = sum_k (x[n][k]*outnorm[n]) * W1[k][j]   (64x64) ----
__global__ __launch_bounds__(256) void k_gemm1(const float* __restrict__ x,
                                               const float* __restrict__ W1) {
    __shared__ float Ws[64 * 64];
    __shared__ float xs[64][68];
    int tid = threadIdx.x;
    int nb  = blockIdx.x * 64;

    #pragma unroll
    for (int r = 0; r < 4; r++) {
        int idx = tid + r * 256;
        reinterpret_cast<float4*>(Ws)[idx] =
            reinterpret_cast<const float4*>(W1)[idx];
    }
    #pragma unroll
    for (int r = 0; r < 4; r++) {
        int idx = tid + r * 256;
        int n = idx >> 4, k4 = idx & 15;
        int node = nb + n;
        float4 v = make_float4(0.f, 0.f, 0.f, 0.f);
        float s = 0.f;
        if (node < NN) {
            v = reinterpret_cast<const float4*>(x)[node * 16 + k4];
            s = g_outnorm[node];
        }
        xs[k4 * 4 + 0][n] = v.x * s;
        xs[k4 * 4 + 1][n] = v.y * s;
        xs[k4 * 4 + 2][n] = v.z * s;
        xs[k4 * 4 + 3][n] = v.w * s;
    }
    __syncthreads();

    int tx = tid & 15;
    int ty = tid >> 4;
    float acc[4][4] = {};
    #pragma unroll
    for (int k = 0; k < 64; k++) {
        float4 wv = *reinterpret_cast<const float4*>(&Ws[k * 64 + tx * 4]);
        float4 xv = *reinterpret_cast<const float4*>(&xs[k][ty * 4]);
        float xr[4] = {xv.x, xv.y, xv.z, xv.w};
        float wr[4] = {wv.x, wv.y, wv.z, wv.w};
        #pragma unroll
        for (int i = 0; i < 4; i++)
            #pragma unroll
            for (int j = 0; j < 4; j++)
                acc[i][j] += xr[i] * wr[j];
    }
    #pragma unroll
    for (int i = 0; i < 4; i++) {
        int node = nb + ty * 4 + i;
        if (node < NN) {
            float4 o = make_float4(acc[i][0], acc[i][1], acc[i][2], acc[i][3]);
            reinterpret_cast<float4*>(g_h1)[node * 16 + tx] = o;
        }
    }
}

// ---- gather SpMM layer 1: agg1[n] = sum_{s in in(n)} h1[s]  (64 floats, warp/node) ----
__global__ __launch_bounds__(256) void k_gather1() {
    int w = (blockIdx.x * blockDim.x + threadIdx.x) >> 5;
    int lane = threadIdx.x & 31;
    if (w >= NN) return;
    int beg = g_rowptr[w], end = g_rowptr[w + 1];

    float2 a0 = {0.f, 0.f}, a1 = {0.f, 0.f}, a2 = {0.f, 0.f}, a3 = {0.f, 0.f};
    for (int c = beg; c < end; c += 32) {
        int idx = c + lane;
        int sreg = (idx < end) ? g_csr_src[idx] : 0;
        int n = end - c; if (n > 32) n = 32;
        int j = 0;
        for (; j + 4 <= n; j += 4) {
            int s0 = __shfl_sync(0xffffffffu, sreg, j + 0);
            int s1 = __shfl_sync(0xffffffffu, sreg, j + 1);
            int s2 = __shfl_sync(0xffffffffu, sreg, j + 2);
            int s3 = __shfl_sync(0xffffffffu, sreg, j + 3);
            float2 v0 = *reinterpret_cast<const float2*>(&g_h1[s0 * 64 + lane * 2]);
            float2 v1 = *reinterpret_cast<const float2*>(&g_h1[s1 * 64 + lane * 2]);
            float2 v2 = *reinterpret_cast<const float2*>(&g_h1[s2 * 64 + lane * 2]);
            float2 v3 = *reinterpret_cast<const float2*>(&g_h1[s3 * 64 + lane * 2]);
            a0.x += v0.x; a0.y += v0.y;
            a1.x += v1.x; a1.y += v1.y;
            a2.x += v2.x; a2.y += v2.y;
            a3.x += v3.x; a3.y += v3.y;
        }
        for (; j < n; j++) {
            int s = __shfl_sync(0xffffffffu, sreg, j);
            float2 v = *reinterpret_cast<const float2*>(&g_h1[s * 64 + lane * 2]);
            a0.x += v.x; a0.y += v.y;
        }
    }
    float2 r;
    r.x = (a0.x + a1.x) + (a2.x + a3.x);
    r.y = (a0.y + a1.y) + (a2.y + a3.y);
    *reinterpret_cast<float2*>(&g_agg1[w * 64 + lane * 2]) = r;
}

// ---- Fused layer-1 epilogue + GEMM2 (64 -> 32) ----
__global__ __launch_bounds__(256) void k_gemm2(const float* __restrict__ W2,
                                               const float* __restrict__ b1) {
    __shared__ float Ws[64 * 32];
    __shared__ float xs[64][68];
    int tid = threadIdx.x;
    int nb  = blockIdx.x * 64;

    #pragma unroll
    for (int r = 0; r < 2; r++) {
        int idx = tid + r * 256;
        reinterpret_cast<float4*>(Ws)[idx] =
            reinterpret_cast<const float4*>(W2)[idx];
    }
    #pragma unroll
    for (int r = 0; r < 4; r++) {
        int idx = tid + r * 256;
        int n = idx >> 4, k4 = idx & 15;
        int node = nb + n;
        float4 v = make_float4(0.f, 0.f, 0.f, 0.f);
        if (node < NN) {
            v = reinterpret_cast<const float4*>(g_agg1)[node * 16 + k4];
            float in_n = g_innorm[node];
            float on   = g_outnorm[node];
            float4 bb  = reinterpret_cast<const float4*>(b1)[k4];
            v.x = fmaxf(fmaf(v.x, in_n, bb.x), 0.f) * on;
            v.y = fmaxf(fmaf(v.y, in_n, bb.y), 0.f) * on;
            v.z = fmaxf(fmaf(v.z, in_n, bb.z), 0.f) * on;
            v.w = fmaxf(fmaf(v.w, in_n, bb.w), 0.f) * on;
        }
        xs[k4 * 4 + 0][n] = v.x;
        xs[k4 * 4 + 1][n] = v.y;
        xs[k4 * 4 + 2][n] = v.z;
        xs[k4 * 4 + 3][n] = v.w;
    }
    __syncthreads();

    int tx = tid & 7;
    int ty = tid >> 3;
    float acc[2][4] = {};
    #pragma unroll
    for (int k = 0; k < 64; k++) {
        float4 wv = *reinterpret_cast<const float4*>(&Ws[k * 32 + tx * 4]);
        float x0 = xs[k][ty * 2 + 0];
        float x1 = xs[k][ty * 2 + 1];
        acc[0][0] += x0 * wv.x; acc[0][1] += x0 * wv.y;
        acc[0][2] += x0 * wv.z; acc[0][3] += x0 * wv.w;
        acc[1][0] += x1 * wv.x; acc[1][1] += x1 * wv.y;
        acc[1][2] += x1 * wv.z; acc[1][3] += x1 * wv.w;
    }
    #pragma unroll
    for (int i = 0; i < 2; i++) {
        int node = nb + ty * 2 + i;
        if (node < NN) {
            float4 o = make_float4(acc[i][0], acc[i][1], acc[i][2], acc[i][3]);
            reinterpret_cast<float4*>(g_h2)[node * 8 + tx] = o;
        }
    }
}

// ---- gather SpMM layer 2 + final epilogue: out[n] = (sum h2[s]) * innorm[n] + b2 ----
__global__ __launch_bounds__(256) void k_gather2(const float* __restrict__ b2,
                                                 float* __restrict__ out) {
    int w = (blockIdx.x * blockDim.x + threadIdx.x) >> 5;
    int lane = threadIdx.x & 31;
    if (w >= NN) return;
    int beg = g_rowptr[w], end = g_rowptr[w + 1];

    float a0 = 0.f, a1 = 0.f, a2 = 0.f, a3 = 0.f;
    for (int c = beg; c < end; c += 32) {
        int idx = c + lane;
        int sreg = (idx < end) ? g_csr_src[idx] : 0;
        int n = end - c; if (n > 32) n = 32;
        int j = 0;
        for (; j + 4 <= n; j += 4) {
            int s0 = __shfl_sync(0xffffffffu, sreg, j + 0);
            int s1 = __shfl_sync(0xffffffffu, sreg, j + 1);
            int s2 = __shfl_sync(0xffffffffu, sreg, j + 2);
            int s3 = __shfl_sync(0xffffffffu, sreg, j + 3);
            a0 += g_h2[s0 * 32 + lane];
            a1 += g_h2[s1 * 32 + lane];
            a2 += g_h2[s2 * 32 + lane];
            a3 += g_h2[s3 * 32 + lane];
        }
        for (; j < n; j++) {
            int s = __shfl_sync(0xffffffffu, sreg, j);
            a0 += g_h2[s * 32 + lane];
        }
    }
    float acc = (a0 + a1) + (a2 + a3);
    out[w * 32 + lane] = fmaf(acc, g_innorm[w], b2[lane]);
}

extern "C" void kernel_launch(void* const* d_in, const int* in_sizes, int n_in,
                              void* d_out, int out_size) {
    const float* x   = (const float*)d_in[0];
    const int*   src = (const int*)  d_in[1];
    const int*   dst = (const int*)  d_in[2];
    const float* W1  = (const float*)d_in[3];
    const float* b1  = (const float*)d_in[4];
    const float* W2  = (const float*)d_in[5];
    const float* b2  = (const float*)d_in[6];
    float* out = (float*)d_out;

    const int T = 256;
    k_zero  <<<(NN + T - 1) / T, T>>>();
    k_deg   <<<(NE + T - 1) / T, T>>>(src, dst);
    k_norm  <<<(NN + T - 1) / T, T>>>();
    k_scan1 <<<SCAN_NBLK, 256>>>();
    k_scan2 <<<1, 128>>>();
    k_scan3 <<<(NN + T - 1) / T, T>>>();
    k_bucket<<<(NE + T - 1) / T, T>>>(src, dst);
    k_gemm1 <<<(NN + 63) / 64, 256>>>(x, W1);
    k_gather1<<<(NN * 32 + T - 1) / T, T>>>();
    k_gemm2 <<<(NN + 63) / 64, 256>>>(W2, b1);
    k_gather2<<<(NN * 32 + T - 1) / T, T>>>(b2, out);
}